// round 8
// baseline (speedup 1.0000x reference)
#include <cuda_runtime.h>
#include <math.h>
#include <stdint.h>

#define HH 65
#define WW 65
#define HW 4225
#define NH 8
#define DK 512
#define RW 33
#define HRW 2145
#define DHID 4096

// ---------------- scratch (device globals) ----------------
__device__ float g_q[DHID];
__device__ float g_up[8 * 4096];
__device__ float g_qb[NH];
__device__ float g_A0p[8 * NH * HW];
__device__ float g_A0[NH * HW];
__device__ float g_Wt1[DK * 1024];        // tf32 bits, [k][br*512+o]
__device__ float g_Wt2[2 * 9 * DK * DK];  // tf32 bits, [br*9+t][i][o]
__device__ float g_F1[2 * DK * HW];       // fp32 (for residual)
__device__ uint32_t g_F1t[2 * DK * HW];   // tf32 bits of relu(F1)
__device__ float g_F2[2 * DK * HW];
__device__ float g_F3p[2 * 8 * NH * HW];
__device__ float g_F3[2 * NH * HW];
__device__ float g_filt[2][NH * HRW];
__device__ float2 g_Fr[NH * HRW];
__device__ float2 g_Af[NH * HRW];
__device__ float2 g_Gr[NH * HRW];
__device__ float g_A[NH * HW];
__device__ float g_P[NH * HW];
__device__ float g_m[NH * DK];
__device__ float g_x[DHID];

#define TWO_PI 6.28318530717958647692f

__device__ __forceinline__ uint32_t f2tf32(float f) {
    uint32_t u;
    asm("cvt.rna.tf32.f32 %0, %1;" : "=r"(u) : "f"(f));
    return u;
}

__device__ __forceinline__ void mma_tf32(
    float& c0, float& c1, float& c2, float& c3,
    uint32_t a0, uint32_t a1, uint32_t a2, uint32_t a3,
    uint32_t b0, uint32_t b1) {
    asm volatile(
        "mma.sync.aligned.m16n8k8.row.col.f32.tf32.tf32.f32 "
        "{%0,%1,%2,%3},{%4,%5,%6,%7},{%8,%9},{%0,%1,%2,%3};"
        : "+f"(c0), "+f"(c1), "+f"(c2), "+f"(c3)
        : "r"(a0), "r"(a1), "r"(a2), "r"(a3), "r"(b0), "r"(b1));
}

__device__ __forceinline__ void cp_async4(uint32_t smem_addr, const void* gptr, int src_bytes) {
    asm volatile("cp.async.ca.shared.global [%0], [%1], 4, %2;\n"
                 :: "r"(smem_addr), "l"(gptr), "r"(src_bytes));
}
__device__ __forceinline__ void cp_commit() {
    asm volatile("cp.async.commit_group;\n" ::: "memory");
}
template <int N>
__device__ __forceinline__ void cp_wait() {
    asm volatile("cp.async.wait_group %0;\n" :: "n"(N) : "memory");
}

// ---------------- q = Wq @ Q + bq ----------------
__global__ void k_qproj(const float* __restrict__ Q, const float* __restrict__ Wq,
                        const float* __restrict__ bq) {
    int r = blockIdx.x * 8 + (threadIdx.x >> 5);
    int lane = threadIdx.x & 31;
    const float* wr = Wq + r * DK;
    float acc = 0.f;
    for (int c = lane; c < DK; c += 32) acc += wr[c] * Q[c];
    #pragma unroll
    for (int o = 16; o > 0; o >>= 1) acc += __shfl_down_sync(0xffffffffu, acc, o);
    if (lane == 0) g_q[r] = acc + bq[r];
}

// ---------------- qb[h] = q_h . bk_h ----------------
__global__ void k_qb(const float* __restrict__ bk) {
    int h = threadIdx.x >> 5, lane = threadIdx.x & 31;
    float acc = 0.f;
    for (int d = lane; d < DK; d += 32) acc += g_q[h * DK + d] * bk[h * DK + d];
    #pragma unroll
    for (int o = 16; o > 0; o >>= 1) acc += __shfl_down_sync(0xffffffffu, acc, o);
    if (lane == 0) g_qb[h] = acc;
}

// ---------------- u partials ----------------
__global__ void k_u(const float* __restrict__ Wk) {
    int h = blockIdx.x, p = blockIdx.y;
    int tid = threadIdx.x;  // 512
    __shared__ float qs[64];
    if (tid < 64) qs[tid] = g_q[h * DK + p * 64 + tid];
    __syncthreads();
    float acc = 0.f;
    const float* wb = Wk + h * DK * DK + (p * 64) * DK + tid;
    #pragma unroll 8
    for (int d = 0; d < 64; d++) acc += wb[d * DK] * qs[d];
    g_up[p * 4096 + h * DK + tid] = acc;
}

// ---------------- A0 partials over c-chunks of 64 ----------------
__global__ void k_A0p(const float* __restrict__ K) {
    __shared__ float us[NH * 64];
    int tid = threadIdx.x;
    int c0 = blockIdx.y * 64;
    for (int i = tid; i < NH * 64; i += 256) {
        int h = i >> 6, c = i & 63;
        float s = 0.f;
        #pragma unroll
        for (int p = 0; p < 8; p++) s += g_up[p * 4096 + h * DK + c0 + c];
        us[i] = s;
    }
    __syncthreads();
    int s = blockIdx.x * 256 + tid;
    if (s >= HW) return;
    float acc[NH] = {};
    for (int c = 0; c < 64; c++) {
        float kv = K[(c0 + c) * HW + s];
        #pragma unroll
        for (int h = 0; h < NH; h++) acc[h] += us[h * 64 + c] * kv;
    }
    #pragma unroll
    for (int h = 0; h < NH; h++) g_A0p[blockIdx.y * NH * HW + h * HW + s] = acc[h];
}

__global__ void k_A0red() {
    int idx = blockIdx.x * 256 + threadIdx.x;
    if (idx >= NH * HW) return;
    int h = idx / HW;
    float s = 0.f;
    #pragma unroll
    for (int p = 0; p < 8; p++) s += g_A0p[p * NH * HW + idx];
    g_A0[idx] = (s + g_qb[h]) * 0.04419417382415922f;
}

// ---------------- tiled weight transposes (store tf32 bits) ----------------
__global__ void k_tr1(const float* __restrict__ amp1, const float* __restrict__ pha1) {
    __shared__ float tile[32][33];
    int br = blockIdx.z;
    const float* src = br ? pha1 : amp1;
    int o0 = blockIdx.x * 32, i0 = blockIdx.y * 32;
    int tx = threadIdx.x, ty = threadIdx.y;
    #pragma unroll
    for (int r = 0; r < 32; r += 8)
        tile[ty + r][tx] = src[(o0 + ty + r) * DK + i0 + tx];
    __syncthreads();
    #pragma unroll
    for (int r = 0; r < 32; r += 8)
        g_Wt1[(i0 + ty + r) * 1024 + br * DK + o0 + tx] = __uint_as_float(f2tf32(tile[tx][ty + r]));
}

__global__ void k_tr2(const float* __restrict__ amp2, const float* __restrict__ pha2) {
    __shared__ float tile[32][33];
    int bt = blockIdx.x;           // br*9 + t
    int br = bt / 9, t = bt % 9;
    const float* src = br ? pha2 : amp2;
    int o0 = blockIdx.y * 32, i0 = blockIdx.z * 32;
    int tx = threadIdx.x, ty = threadIdx.y;
    #pragma unroll
    for (int r = 0; r < 32; r += 8)
        tile[ty + r][tx] = src[((o0 + ty + r) * DK + i0 + tx) * 9 + t];
    __syncthreads();
    #pragma unroll
    for (int r = 0; r < 32; r += 8)
        g_Wt2[((size_t)bt * DK + i0 + ty + r) * DK + o0 + tx] = __uint_as_float(f2tf32(tile[tx][ty + r]));
}

// ---------------- tf32 tensor-core GEMM / implicit conv ----------------
// MODE 0: 1x1 conv, A=g_Wt1 (tf32 bits, Mstride 1024), B=Kin (fp32, cvt at stage),
//         writes g_F1 (fp32) + g_F1t (tf32 bits of relu).   Synchronous loop.
// MODE 1: 3x3 conv, A=g_Wt2[z] (tf32 bits), B=g_F1t[z] (tf32 bits, pure copy),
//         residual +g_F1, writes g_F2.   cp.async double-buffered pipeline.

#define DECL_ACC(M,N) float c##M##N##x = 0.f, c##M##N##y = 0.f, c##M##N##z = 0.f, c##M##N##w = 0.f

#define LOADA(M) uint32_t a##M##0 = Af[r0][wm + M*16 + g], a##M##1 = Af[r0][wm + M*16 + g + 8], \
                          a##M##2 = Af[r1][wm + M*16 + g], a##M##3 = Af[r1][wm + M*16 + g + 8]
#define LOADB(N) uint32_t b##N##0 = Bf[r0][wn + N*8 + g], b##N##1 = Bf[r1][wn + N*8 + g]

#define DOMMA(M,N) mma_tf32(c##M##N##x, c##M##N##y, c##M##N##z, c##M##N##w, \
                            a##M##0, a##M##1, a##M##2, a##M##3, b##N##0, b##N##1)

#define MMA_ALL() do { \
    _Pragma("unroll") \
    for (int kf = 0; kf < 2; kf++) { \
        int r0 = kf * 8 + tg, r1 = r0 + 4; \
        LOADA(0); LOADA(1); LOADA(2); LOADA(3); \
        LOADB(0); LOADB(1); LOADB(2); LOADB(3); \
        DOMMA(0,0); DOMMA(0,1); DOMMA(0,2); DOMMA(0,3); \
        DOMMA(1,0); DOMMA(1,1); DOMMA(1,2); DOMMA(1,3); \
        DOMMA(2,0); DOMMA(2,1); DOMMA(2,2); DOMMA(2,3); \
        DOMMA(3,0); DOMMA(3,1); DOMMA(3,2); DOMMA(3,3); \
    } \
} while (0)

#define STORE1(val, mrow, nc) do { \
    if (MODE == 0) { \
        float v_ = (val); \
        Yb[(size_t)(mrow) * HW + (nc)] = v_; \
        g_F1t[(size_t)(mrow) * HW + (nc)] = f2tf32(fmaxf(v_, 0.f)); \
    } else { \
        Yb[(size_t)(mrow) * HW + (nc)] = (val) + Rb[(size_t)(mrow) * HW + (nc)]; \
    } \
} while (0)

#define EPI(M,N) do { \
    int mrow = m0 + wm + M*16 + g; \
    int nc = n0 + wn + N*8 + tg*2; \
    if (nc < HW) { \
        STORE1(c##M##N##x, mrow, nc); \
        STORE1(c##M##N##z, mrow + 8, nc); \
        if (nc + 1 < HW) { \
            STORE1(c##M##N##y, mrow, nc + 1); \
            STORE1(c##M##N##w, mrow + 8, nc + 1); \
        } \
    } \
} while (0)

template <int MODE>
__global__ void __launch_bounds__(256) k_mma(const float* __restrict__ Kin) {
    __shared__ uint32_t As[2][16][132];
    __shared__ uint32_t Bs[2][16][132];
    int tid = threadIdx.x;
    int n0 = blockIdx.x * 128, m0 = blockIdx.y * 128;
    int z = blockIdx.z;

    int col = tid & 127;
    int krow0 = tid >> 7;         // 0 or 1
    int n = n0 + col;
    bool nvalid = n < HW;
    int ny = n / WW, nx = n - ny * WW;

    int warp = tid >> 5, lane = tid & 31;
    int wm = (warp & 1) * 64, wn = (warp >> 1) * 32;
    int g = lane >> 2, tg = lane & 3;

    float* Yb;
    const float* Rb;
    if (MODE == 0) { Yb = g_F1; Rb = g_F1; }
    else { Yb = g_F2 + (size_t)z * DK * HW; Rb = g_F1 + (size_t)z * DK * HW; }

    DECL_ACC(0,0); DECL_ACC(0,1); DECL_ACC(0,2); DECL_ACC(0,3);
    DECL_ACC(1,0); DECL_ACC(1,1); DECL_ACC(1,2); DECL_ACC(1,3);
    DECL_ACC(2,0); DECL_ACC(2,1); DECL_ACC(2,2); DECL_ACC(2,3);
    DECL_ACC(3,0); DECL_ACC(3,1); DECL_ACC(3,2); DECL_ACC(3,3);

    if (MODE == 0) {
        // synchronous loop, single buffer; A pre-cvt bits, B needs cvt from fp32 K
        const uint32_t* Wt1u = (const uint32_t*)g_Wt1;
        for (int kc = 0; kc < DK; kc += 16) {
            #pragma unroll
            for (int i = 0; i < 8; i++) {
                int kr = i * 2 + krow0;
                As[0][kr][col] = Wt1u[(size_t)(kc + kr) * 1024 + m0 + col];
                Bs[0][kr][col] = f2tf32(nvalid ? Kin[(kc + kr) * HW + n] : 0.f);
            }
            __syncthreads();
            const uint32_t (*Af)[132] = As[0];
            const uint32_t (*Bf)[132] = Bs[0];
            MMA_ALL();
            __syncthreads();
        }
    } else {
        // cp.async double-buffered pipeline over 9 taps x 32 k-slices = 288 slices
        const int S = 9 * 32;
        uint32_t as_base = (uint32_t)__cvta_generic_to_shared(&As[0][0][0]);
        uint32_t bs_base = (uint32_t)__cvta_generic_to_shared(&Bs[0][0][0]);
        const uint32_t* Wt2u = (const uint32_t*)g_Wt2;
        const uint32_t* F1tz = g_F1t + (size_t)z * DK * HW;

        auto stage = [&](int buf, int s) {
            int t = s >> 5;
            int kc = (s & 31) << 4;
            int dy = t / 3 - 1, dx = t % 3 - 1;
            int yy = ny + dy, xx = nx + dx;
            bool ok = nvalid && (unsigned)yy < HH && (unsigned)xx < WW;
            int src = ok ? (yy * WW + xx) : 0;
            int okb = ok ? 4 : 0;
            const uint32_t* wrow = Wt2u + ((size_t)(z * 9 + t) * DK + kc) * DK + m0 + col;
            const uint32_t* xrow = F1tz + (size_t)kc * HW + src;
            uint32_t abase = as_base + (((buf * 16) * 132 + col) << 2);
            uint32_t bbase = bs_base + (((buf * 16) * 132 + col) << 2);
            #pragma unroll
            for (int i = 0; i < 8; i++) {
                int kr = i * 2 + krow0;
                cp_async4(abase + kr * (132 << 2), wrow + (size_t)kr * DK, 4);
                cp_async4(bbase + kr * (132 << 2), xrow + (size_t)kr * HW, okb);
            }
        };

        stage(0, 0);
        cp_commit();
        for (int s = 0; s < S; s++) {
            int buf = s & 1;
            if (s + 1 < S) {
                stage(1 - buf, s + 1);
                cp_commit();
                cp_wait<1>();
            } else {
                cp_wait<0>();
            }
            __syncthreads();
            const uint32_t (*Af)[132] = As[buf];
            const uint32_t (*Bf)[132] = Bs[buf];
            MMA_ALL();
            __syncthreads();
        }
    }

    EPI(0,0); EPI(0,1); EPI(0,2); EPI(0,3);
    EPI(1,0); EPI(1,1); EPI(1,2); EPI(1,3);
    EPI(2,0); EPI(2,1); EPI(2,2); EPI(2,3);
    EPI(3,0); EPI(3,1); EPI(3,2); EPI(3,3);
}

// ---------------- F3 partials over c-chunks of 64 ----------------
__global__ void k_f3p(const float* __restrict__ amp3, const float* __restrict__ pha3) {
    __shared__ float ws[NH * 64];
    int tid = threadIdx.x;
    int c0 = blockIdx.y * 64;
    int br = blockIdx.z;
    const float* W3 = br ? pha3 : amp3;
    const float* F2b = g_F2 + (size_t)br * DK * HW;
    for (int i = tid; i < NH * 64; i += 256) {
        int h = i >> 6, c = i & 63;
        ws[i] = W3[h * DK + c0 + c];
    }
    __syncthreads();
    int s = blockIdx.x * 256 + tid;
    if (s >= HW) return;
    float acc[NH] = {};
    for (int c = 0; c < 64; c++) {
        float v = fmaxf(F2b[(c0 + c) * HW + s], 0.f);
        #pragma unroll
        for (int h = 0; h < NH; h++) acc[h] += ws[h * 64 + c] * v;
    }
    #pragma unroll
    for (int h = 0; h < NH; h++)
        g_F3p[((size_t)br * 8 + blockIdx.y) * NH * HW + h * HW + s] = acc[h];
}

__global__ void k_f3red() {
    int idx = blockIdx.x * 256 + threadIdx.x;
    if (idx >= NH * HW) return;
    int br = blockIdx.y;
    const float* p = g_F3p + (size_t)br * 8 * NH * HW;
    float s = 0.f;
    #pragma unroll
    for (int i = 0; i < 8; i++) s += p[i * NH * HW + idx];
    g_F3[br * NH * HW + idx] = fmaxf(s, 0.f);
}

// ---------------- down-proj (warp per output j) ----------------
__global__ void k_down(const float* __restrict__ Wd1, const float* __restrict__ bd1,
                       const float* __restrict__ Wd2, const float* __restrict__ bd2) {
    int warp = threadIdx.x >> 5, lane = threadIdx.x & 31;
    int j = blockIdx.x * 8 + warp;
    int br = blockIdx.y;
    if (j >= HRW) return;
    const float* Wd = br ? Wd2 : Wd1;
    const float* bd = br ? bd2 : bd1;
    const float* F3b = g_F3 + br * NH * HW;
    const float* wr = Wd + (size_t)j * HW;
    float acc[NH] = {};
    for (int s = lane; s < HW; s += 32) {
        float wv = wr[s];
        #pragma unroll
        for (int h = 0; h < NH; h++) acc[h] += wv * F3b[h * HW + s];
    }
    #pragma unroll
    for (int h = 0; h < NH; h++) {
        #pragma unroll
        for (int o = 16; o > 0; o >>= 1) acc[h] += __shfl_down_sync(0xffffffffu, acc[h], o);
    }
    if (lane == 0) {
        float b = bd[j];
        #pragma unroll
        for (int h = 0; h < NH; h++) g_filt[br][h * HRW + j] = acc[h] + b;
    }
}

// ---------------- FFT chain ----------------
__global__ void k_fftrow() {
    int hy = blockIdx.x;
    int h = hy / HH, y = hy % HH;
    __shared__ float row[HH], twc[HH], tws[HH];
    int tid = threadIdx.x;  // 64
    for (int i = tid; i < HH; i += 64) {
        row[i] = g_A0[h * HW + y * WW + i];
        float sv, cv;
        sincosf(TWO_PI * (float)i / 65.f, &sv, &cv);
        twc[i] = cv; tws[i] = sv;
    }
    __syncthreads();
    if (tid < RW) {
        float re = 0.f, im = 0.f;
        for (int x = 0; x < HH; x++) {
            int t = (tid * x) % 65;
            re += row[x] * twc[t];
            im -= row[x] * tws[t];
        }
        g_Fr[h * HRW + y * RW + tid] = make_float2(re, im);
    }
}

__global__ void k_fftcol_mod() {
    __shared__ float twc[HH], tws[HH];
    for (int i = threadIdx.x; i < HH; i += 256) {
        float sv, cv;
        sincosf(TWO_PI * (float)i / 65.f, &sv, &cv);
        twc[i] = cv; tws[i] = sv;
    }
    __syncthreads();
    int idx = blockIdx.x * 256 + threadIdx.x;
    if (idx >= NH * HRW) return;
    int h = idx / HRW, r = idx % HRW;
    int ky = r / RW, kx = r % RW;
    const float2* fr = g_Fr + h * HRW + kx;
    float re = 0.f, im = 0.f;
    for (int y = 0; y < HH; y++) {
        int t = (ky * y) % 65;
        float c = twc[t], s = tws[t];
        float2 f = fr[y * RW];
        re += f.x * c + f.y * s;
        im += f.y * c - f.x * s;
    }
    float mag = sqrtf(re * re + im * im);
    float ang = atan2f(im, re);
    float a = g_filt[0][idx] * mag;
    float p = g_filt[1][idx] * ang;
    float sp, cp;
    sincosf(p, &sp, &cp);
    g_Af[idx] = make_float2(a * cp, a * sp);
}

__global__ void k_invcol() {
    __shared__ float twc[HH], tws[HH];
    for (int i = threadIdx.x; i < HH; i += 256) {
        float sv, cv;
        sincosf(TWO_PI * (float)i / 65.f, &sv, &cv);
        twc[i] = cv; tws[i] = sv;
    }
    __syncthreads();
    int idx = blockIdx.x * 256 + threadIdx.x;
    if (idx >= NH * HRW) return;
    int h = idx / HRW, r = idx % HRW;
    int y = r / RW, kx = r % RW;
    const float2* af = g_Af + h * HRW + kx;
    float re = 0.f, im = 0.f;
    for (int ky = 0; ky < HH; ky++) {
        int t = (ky * y) % 65;
        float c = twc[t], s = tws[t];
        float2 f = af[ky * RW];
        re += f.x * c - f.y * s;
        im += f.y * c + f.x * s;
    }
    g_Gr[idx] = make_float2(re * (1.f / 65.f), im * (1.f / 65.f));
}

__global__ void k_invrow() {
    __shared__ float twc[HH], tws[HH];
    for (int i = threadIdx.x; i < HH; i += 256) {
        float sv, cv;
        sincosf(TWO_PI * (float)i / 65.f, &sv, &cv);
        twc[i] = cv; tws[i] = sv;
    }
    __syncthreads();
    int idx = blockIdx.x * 256 + threadIdx.x;
    if (idx >= NH * HW) return;
    int h = idx / HW, s = idx % HW;
    int y = s / WW, x = s % WW;
    const float2* gp = g_Gr + h * HRW + y * RW;
    float acc = gp[0].x;
    for (int k = 1; k < RW; k++) {
        int t = (k * x) % 65;
        acc += 2.f * (gp[k].x * twc[t] - gp[k].y * tws[t]);
    }
    g_A[idx] = acc * (1.f / 65.f);
}

// ---------------- softmax per head ----------------
__global__ void k_softmax() {
    int h = blockIdx.x, tid = threadIdx.x;
    __shared__ float red[256];
    const float* a = g_A + h * HW;
    float* p = g_P + h * HW;
    float mx = -3.4e38f;
    for (int s = tid; s < HW; s += 256) mx = fmaxf(mx, a[s]);
    red[tid] = mx;
    __syncthreads();
    for (int st = 128; st > 0; st >>= 1) {
        if (tid < st) red[tid] = fmaxf(red[tid], red[tid + st]);
        __syncthreads();
    }
    mx = red[0];
    __syncthreads();
    float sum = 0.f;
    for (int s = tid; s < HW; s += 256) {
        float e = expf(a[s] - mx);
        p[s] = e;
        sum += e;
    }
    red[tid] = sum;
    __syncthreads();
    for (int st = 128; st > 0; st >>= 1) {
        if (tid < st) red[tid] += red[tid + st];
        __syncthreads();
    }
    float inv = 1.f / red[0];
    for (int s = tid; s < HW; s += 256) p[s] *= inv;
}

// ---------------- m[h,c] = sum_s P[h,s]*K[c,s] ----------------
__global__ void k_m(const float* __restrict__ K) {
    int c = blockIdx.x * 8 + (threadIdx.x >> 5);
    int lane = threadIdx.x & 31;
    const float* kr = K + c * HW;
    float acc[NH] = {};
    for (int s = lane; s < HW; s += 32) {
        float kv = kr[s];
        #pragma unroll
        for (int h = 0; h < NH; h++) acc[h] += kv * g_P[h * HW + s];
    }
    #pragma unroll
    for (int h = 0; h < NH; h++) {
        #pragma unroll
        for (int o = 16; o > 0; o >>= 1) acc[h] += __shfl_down_sync(0xffffffffu, acc[h], o);
    }
    if (lane == 0) {
        #pragma unroll
        for (int h = 0; h < NH; h++) g_m[h * DK + c] = acc[h];
    }
}

__global__ void k_vproj(const float* __restrict__ Wv, const float* __restrict__ bv) {
    int r = blockIdx.x * 8 + (threadIdx.x >> 5);
    int lane = threadIdx.x & 31;
    int h = r >> 9;
    const float* mr = g_m + (h << 9);
    const float* wr = Wv + r * DK;
    float acc = 0.f;
    for (int c = lane; c < DK; c += 32) acc += wr[c] * mr[c];
    #pragma unroll
    for (int o = 16; o > 0; o >>= 1) acc += __shfl_down_sync(0xffffffffu, acc, o);
    if (lane == 0) g_x[r] = acc + bv[r];
}

__global__ void k_out(const float* __restrict__ Wo, const float* __restrict__ bo,
                      float* __restrict__ out) {
    int r = blockIdx.x * 8 + (threadIdx.x >> 5);
    int lane = threadIdx.x & 31;
    const float* wr = Wo + r * DHID;
    float acc = 0.f;
    for (int j = lane; j < DHID; j += 32) acc += wr[j] * g_x[j];
    #pragma unroll
    for (int o = 16; o > 0; o >>= 1) acc += __shfl_down_sync(0xffffffffu, acc, o);
    if (lane == 0) out[r] = acc + bo[r];
}

extern "C" void kernel_launch(void* const* d_in, const int* in_sizes, int n_in,
                              void* d_out, int out_size) {
    const float* Q    = (const float*)d_in[0];
    const float* K    = (const float*)d_in[1];
    const float* Wq   = (const float*)d_in[2];
    const float* bq   = (const float*)d_in[3];
    const float* Wk   = (const float*)d_in[4];
    const float* bk   = (const float*)d_in[5];
    const float* Wv   = (const float*)d_in[6];
    const float* bv   = (const float*)d_in[7];
    const float* Wo   = (const float*)d_in[8];
    const float* bo   = (const float*)d_in[9];
    const float* amp1 = (const float*)d_in[10];
    const float* amp2 = (const float*)d_in[11];
    const float* amp3 = (const float*)d_in[12];
    const float* pha1 = (const float*)d_in[13];
    const float* pha2 = (const float*)d_in[14];
    const float* pha3 = (const float*)d_in[15];
    const float* Wd1  = (const float*)d_in[16];
    const float* bd1  = (const float*)d_in[17];
    const float* Wd2  = (const float*)d_in[18];
    const float* bd2  = (const float*)d_in[19];
    float* out = (float*)d_out;

    // attention-score path
    k_qproj<<<512, 256>>>(Q, Wq, bq);
    k_qb<<<1, 256>>>(bk);
    k_u<<<dim3(8, 8), 512>>>(Wk);
    k_A0p<<<dim3(17, 8), 256>>>(K);
    k_A0red<<<133, 256>>>();

    // weight reshuffles (both branches), stored as tf32 bits
    k_tr1<<<dim3(16, 16, 2), dim3(32, 8)>>>(amp1, pha1);
    k_tr2<<<dim3(18, 16, 16), dim3(32, 8)>>>(amp2, pha2);

    // 1x1 conv, both branches batched as one M=1024 GEMM (MODE 0)
    k_mma<0><<<dim3(34, 8, 1), 256>>>(K);

    // 3x3 conv + residual, branches via blockIdx.z (MODE 1, cp.async pipeline)
    k_mma<1><<<dim3(34, 4, 2), 256>>>(K);

    k_f3p<<<dim3(17, 8, 2), 256>>>(amp3, pha3);
    k_f3red<<<dim3(133, 2), 256>>>();
    k_down<<<dim3(269, 2), 256>>>(Wd1, bd1, Wd2, bd2);

    // spectral filtering
    k_fftrow<<<NH * HH, 64>>>();
    k_fftcol_mod<<<68, 256>>>();
    k_invcol<<<68, 256>>>();
    k_invrow<<<133, 256>>>();
    k_softmax<<<NH, 256>>>();

    // output path
    k_m<<<64, 256>>>(K);
    k_vproj<<<512, 256>>>(Wv, bv);
    k_out<<<64, 256>>>(Wo, bo, out);
}

// round 9
// speedup vs baseline: 1.0410x; 1.0410x over previous
#include <cuda_runtime.h>
#include <math.h>
#include <stdint.h>

#define HH 65
#define WW 65
#define HW 4225
#define NH 8
#define DK 512
#define RW 33
#define HRW 2145
#define DHID 4096

// ---------------- scratch (device globals) ----------------
__device__ float g_q[DHID];
__device__ float g_up[8 * 4096];
__device__ float g_qb[NH];
__device__ float g_A0p[8 * NH * HW];
__device__ float g_A0[NH * HW];
__device__ float g_Wt1[DK * 1024];        // tf32 bits, [k][br*512+o]
__device__ float g_Wt2[2 * 9 * DK * DK];  // tf32 bits, [br*9+t][i][o]
__device__ float g_F1[2 * DK * HW];       // fp32 (for residual)
__device__ uint32_t g_F1t[2 * DK * HW];   // tf32 bits of relu(F1)
__device__ float g_F2[2 * DK * HW];
__device__ float g_F3p[2 * 8 * NH * HW];
__device__ float g_F3[2 * NH * HW];
__device__ float g_filt[2][NH * HRW];
__device__ float2 g_Fr[NH * HRW];
__device__ float2 g_Af[NH * HRW];
__device__ float2 g_Gr[NH * HRW];
__device__ float g_A[NH * HW];
__device__ float g_P[NH * HW];
__device__ float g_m[NH * DK];
__device__ float g_x[DHID];

#define TWO_PI 6.28318530717958647692f

__device__ __forceinline__ uint32_t f2tf32(float f) {
    uint32_t u;
    asm("cvt.rna.tf32.f32 %0, %1;" : "=r"(u) : "f"(f));
    return u;
}

__device__ __forceinline__ void mma_tf32(
    float& c0, float& c1, float& c2, float& c3,
    uint32_t a0, uint32_t a1, uint32_t a2, uint32_t a3,
    uint32_t b0, uint32_t b1) {
    asm volatile(
        "mma.sync.aligned.m16n8k8.row.col.f32.tf32.tf32.f32 "
        "{%0,%1,%2,%3},{%4,%5,%6,%7},{%8,%9},{%0,%1,%2,%3};"
        : "+f"(c0), "+f"(c1), "+f"(c2), "+f"(c3)
        : "r"(a0), "r"(a1), "r"(a2), "r"(a3), "r"(b0), "r"(b1));
}

// ---------------- q = Wq @ Q + bq ----------------
__global__ void k_qproj(const float* __restrict__ Q, const float* __restrict__ Wq,
                        const float* __restrict__ bq) {
    int r = blockIdx.x * 8 + (threadIdx.x >> 5);
    int lane = threadIdx.x & 31;
    const float* wr = Wq + r * DK;
    float acc = 0.f;
    for (int c = lane; c < DK; c += 32) acc += wr[c] * Q[c];
    #pragma unroll
    for (int o = 16; o > 0; o >>= 1) acc += __shfl_down_sync(0xffffffffu, acc, o);
    if (lane == 0) g_q[r] = acc + bq[r];
}

// ---------------- qb[h] = q_h . bk_h ----------------
__global__ void k_qb(const float* __restrict__ bk) {
    int h = threadIdx.x >> 5, lane = threadIdx.x & 31;
    float acc = 0.f;
    for (int d = lane; d < DK; d += 32) acc += g_q[h * DK + d] * bk[h * DK + d];
    #pragma unroll
    for (int o = 16; o > 0; o >>= 1) acc += __shfl_down_sync(0xffffffffu, acc, o);
    if (lane == 0) g_qb[h] = acc;
}

// ---------------- u partials ----------------
__global__ void k_u(const float* __restrict__ Wk) {
    int h = blockIdx.x, p = blockIdx.y;
    int tid = threadIdx.x;  // 512
    __shared__ float qs[64];
    if (tid < 64) qs[tid] = g_q[h * DK + p * 64 + tid];
    __syncthreads();
    float acc = 0.f;
    const float* wb = Wk + h * DK * DK + (p * 64) * DK + tid;
    #pragma unroll 8
    for (int d = 0; d < 64; d++) acc += wb[d * DK] * qs[d];
    g_up[p * 4096 + h * DK + tid] = acc;
}

// ---------------- A0 partials over c-chunks of 64 ----------------
__global__ void k_A0p(const float* __restrict__ K) {
    __shared__ float us[NH * 64];
    int tid = threadIdx.x;
    int c0 = blockIdx.y * 64;
    for (int i = tid; i < NH * 64; i += 256) {
        int h = i >> 6, c = i & 63;
        float s = 0.f;
        #pragma unroll
        for (int p = 0; p < 8; p++) s += g_up[p * 4096 + h * DK + c0 + c];
        us[i] = s;
    }
    __syncthreads();
    int s = blockIdx.x * 256 + tid;
    if (s >= HW) return;
    float acc[NH] = {};
    for (int c = 0; c < 64; c++) {
        float kv = K[(c0 + c) * HW + s];
        #pragma unroll
        for (int h = 0; h < NH; h++) acc[h] += us[h * 64 + c] * kv;
    }
    #pragma unroll
    for (int h = 0; h < NH; h++) g_A0p[blockIdx.y * NH * HW + h * HW + s] = acc[h];
}

__global__ void k_A0red() {
    int idx = blockIdx.x * 256 + threadIdx.x;
    if (idx >= NH * HW) return;
    int h = idx / HW;
    float s = 0.f;
    #pragma unroll
    for (int p = 0; p < 8; p++) s += g_A0p[p * NH * HW + idx];
    g_A0[idx] = (s + g_qb[h]) * 0.04419417382415922f;
}

// ---------------- tiled weight transposes (store tf32 bits) ----------------
__global__ void k_tr1(const float* __restrict__ amp1, const float* __restrict__ pha1) {
    __shared__ float tile[32][33];
    int br = blockIdx.z;
    const float* src = br ? pha1 : amp1;
    int o0 = blockIdx.x * 32, i0 = blockIdx.y * 32;
    int tx = threadIdx.x, ty = threadIdx.y;
    #pragma unroll
    for (int r = 0; r < 32; r += 8)
        tile[ty + r][tx] = src[(o0 + ty + r) * DK + i0 + tx];
    __syncthreads();
    #pragma unroll
    for (int r = 0; r < 32; r += 8)
        g_Wt1[(i0 + ty + r) * 1024 + br * DK + o0 + tx] = __uint_as_float(f2tf32(tile[tx][ty + r]));
}

__global__ void k_tr2(const float* __restrict__ amp2, const float* __restrict__ pha2) {
    __shared__ float tile[32][33];
    int bt = blockIdx.x;           // br*9 + t
    int br = bt / 9, t = bt % 9;
    const float* src = br ? pha2 : amp2;
    int o0 = blockIdx.y * 32, i0 = blockIdx.z * 32;
    int tx = threadIdx.x, ty = threadIdx.y;
    #pragma unroll
    for (int r = 0; r < 32; r += 8)
        tile[ty + r][tx] = src[((o0 + ty + r) * DK + i0 + tx) * 9 + t];
    __syncthreads();
    #pragma unroll
    for (int r = 0; r < 32; r += 8)
        g_Wt2[((size_t)bt * DK + i0 + ty + r) * DK + o0 + tx] = __uint_as_float(f2tf32(tile[tx][ty + r]));
}

// ---------------- tf32 tensor-core GEMM / implicit conv ----------------
// MODE 0: 1x1 conv, synchronous loop (small). Writes g_F1 + g_F1t.
// MODE 1: 3x3 conv, register-prefetch + double-buffer + ONE sync per slice.

#define DECL_ACC(M,N) float c##M##N##x = 0.f, c##M##N##y = 0.f, c##M##N##z = 0.f, c##M##N##w = 0.f

#define LOADA(M) uint32_t a##M##0 = Af[r0][wm + M*16 + g], a##M##1 = Af[r0][wm + M*16 + g + 8], \
                          a##M##2 = Af[r1][wm + M*16 + g], a##M##3 = Af[r1][wm + M*16 + g + 8]
#define LOADB(N) uint32_t b##N##0 = Bf[r0][wn + N*8 + g], b##N##1 = Bf[r1][wn + N*8 + g]

#define DOMMA(M,N) mma_tf32(c##M##N##x, c##M##N##y, c##M##N##z, c##M##N##w, \
                            a##M##0, a##M##1, a##M##2, a##M##3, b##N##0, b##N##1)

#define MMA_ALL() do { \
    _Pragma("unroll") \
    for (int kf = 0; kf < 2; kf++) { \
        int r0 = kf * 8 + tg, r1 = r0 + 4; \
        LOADA(0); LOADA(1); LOADA(2); LOADA(3); \
        LOADB(0); LOADB(1); LOADB(2); LOADB(3); \
        DOMMA(0,0); DOMMA(0,1); DOMMA(0,2); DOMMA(0,3); \
        DOMMA(1,0); DOMMA(1,1); DOMMA(1,2); DOMMA(1,3); \
        DOMMA(2,0); DOMMA(2,1); DOMMA(2,2); DOMMA(2,3); \
        DOMMA(3,0); DOMMA(3,1); DOMMA(3,2); DOMMA(3,3); \
    } \
} while (0)

// Prefetch one 16-row slice into 16 named scalars (no arrays -> no lmem).
#define LDSLICE(s) do { \
    int t_ = (s) >> 5; \
    int kc_ = ((s) & 31) << 4; \
    int dy_ = t_ / 3 - 1, dx_ = t_ % 3 - 1; \
    int yy_ = ny + dy_, xx_ = nx + dx_; \
    bool ok_ = nvalid && (unsigned)yy_ < HH && (unsigned)xx_ < WW; \
    int src_ = ok_ ? (yy_ * WW + xx_) : 0; \
    const uint32_t* wrow_ = Wt2u + ((size_t)(z * 9 + t_) * DK + kc_) * DK + m0 + col; \
    const uint32_t* xrow_ = F1tz + (size_t)kc_ * HW + src_; \
    ra0 = wrow_[(size_t)(0 + krow0) * DK];  rb0 = ok_ ? xrow_[(size_t)(0 + krow0) * HW] : 0u; \
    ra1 = wrow_[(size_t)(2 + krow0) * DK];  rb1 = ok_ ? xrow_[(size_t)(2 + krow0) * HW] : 0u; \
    ra2 = wrow_[(size_t)(4 + krow0) * DK];  rb2 = ok_ ? xrow_[(size_t)(4 + krow0) * HW] : 0u; \
    ra3 = wrow_[(size_t)(6 + krow0) * DK];  rb3 = ok_ ? xrow_[(size_t)(6 + krow0) * HW] : 0u; \
    ra4 = wrow_[(size_t)(8 + krow0) * DK];  rb4 = ok_ ? xrow_[(size_t)(8 + krow0) * HW] : 0u; \
    ra5 = wrow_[(size_t)(10 + krow0) * DK]; rb5 = ok_ ? xrow_[(size_t)(10 + krow0) * HW] : 0u; \
    ra6 = wrow_[(size_t)(12 + krow0) * DK]; rb6 = ok_ ? xrow_[(size_t)(12 + krow0) * HW] : 0u; \
    ra7 = wrow_[(size_t)(14 + krow0) * DK]; rb7 = ok_ ? xrow_[(size_t)(14 + krow0) * HW] : 0u; \
} while (0)

#define STSLICE(buf) do { \
    As[buf][0 + krow0][col] = ra0;  Bs[buf][0 + krow0][col] = rb0; \
    As[buf][2 + krow0][col] = ra1;  Bs[buf][2 + krow0][col] = rb1; \
    As[buf][4 + krow0][col] = ra2;  Bs[buf][4 + krow0][col] = rb2; \
    As[buf][6 + krow0][col] = ra3;  Bs[buf][6 + krow0][col] = rb3; \
    As[buf][8 + krow0][col] = ra4;  Bs[buf][8 + krow0][col] = rb4; \
    As[buf][10 + krow0][col] = ra5; Bs[buf][10 + krow0][col] = rb5; \
    As[buf][12 + krow0][col] = ra6; Bs[buf][12 + krow0][col] = rb6; \
    As[buf][14 + krow0][col] = ra7; Bs[buf][14 + krow0][col] = rb7; \
} while (0)

#define STORE1(val, mrow, nc) do { \
    if (MODE == 0) { \
        float v_ = (val); \
        Yb[(size_t)(mrow) * HW + (nc)] = v_; \
        g_F1t[(size_t)(mrow) * HW + (nc)] = f2tf32(fmaxf(v_, 0.f)); \
    } else { \
        Yb[(size_t)(mrow) * HW + (nc)] = (val) + Rb[(size_t)(mrow) * HW + (nc)]; \
    } \
} while (0)

#define EPI(M,N) do { \
    int mrow = m0 + wm + M*16 + g; \
    int nc = n0 + wn + N*8 + tg*2; \
    if (nc < HW) { \
        STORE1(c##M##N##x, mrow, nc); \
        STORE1(c##M##N##z, mrow + 8, nc); \
        if (nc + 1 < HW) { \
            STORE1(c##M##N##y, mrow, nc + 1); \
            STORE1(c##M##N##w, mrow + 8, nc + 1); \
        } \
    } \
} while (0)

template <int MODE>
__global__ void __launch_bounds__(256) k_mma(const float* __restrict__ Kin) {
    __shared__ uint32_t As[2][16][132];
    __shared__ uint32_t Bs[2][16][132];
    int tid = threadIdx.x;
    int n0 = blockIdx.x * 128, m0 = blockIdx.y * 128;
    int z = blockIdx.z;

    int col = tid & 127;
    int krow0 = tid >> 7;         // 0 or 1
    int n = n0 + col;
    bool nvalid = n < HW;
    int ny = n / WW, nx = n - ny * WW;

    int warp = tid >> 5, lane = tid & 31;
    int wm = (warp & 1) * 64, wn = (warp >> 1) * 32;
    int g = lane >> 2, tg = lane & 3;

    float* Yb;
    const float* Rb;
    if (MODE == 0) { Yb = g_F1; Rb = g_F1; }
    else { Yb = g_F2 + (size_t)z * DK * HW; Rb = g_F1 + (size_t)z * DK * HW; }

    DECL_ACC(0,0); DECL_ACC(0,1); DECL_ACC(0,2); DECL_ACC(0,3);
    DECL_ACC(1,0); DECL_ACC(1,1); DECL_ACC(1,2); DECL_ACC(1,3);
    DECL_ACC(2,0); DECL_ACC(2,1); DECL_ACC(2,2); DECL_ACC(2,3);
    DECL_ACC(3,0); DECL_ACC(3,1); DECL_ACC(3,2); DECL_ACC(3,3);

    if (MODE == 0) {
        // synchronous loop, single buffer; A pre-cvt bits, B needs cvt from fp32 K
        const uint32_t* Wt1u = (const uint32_t*)g_Wt1;
        for (int kc = 0; kc < DK; kc += 16) {
            #pragma unroll
            for (int i = 0; i < 8; i++) {
                int kr = i * 2 + krow0;
                As[0][kr][col] = Wt1u[(size_t)(kc + kr) * 1024 + m0 + col];
                Bs[0][kr][col] = f2tf32(nvalid ? Kin[(kc + kr) * HW + n] : 0.f);
            }
            __syncthreads();
            const uint32_t (*Af)[132] = As[0];
            const uint32_t (*Bf)[132] = Bs[0];
            MMA_ALL();
            __syncthreads();
        }
    } else {
        // register-prefetch + double-buffer, one sync per slice
        const int S = 9 * 32;
        const uint32_t* Wt2u = (const uint32_t*)g_Wt2;
        const uint32_t* F1tz = g_F1t + (size_t)z * DK * HW;
        uint32_t ra0, ra1, ra2, ra3, ra4, ra5, ra6, ra7;
        uint32_t rb0, rb1, rb2, rb3, rb4, rb5, rb6, rb7;
        LDSLICE(0);
        for (int s = 0; s < S; s++) {
            int buf = s & 1;
            STSLICE(buf);
            __syncthreads();
            if (s + 1 < S) LDSLICE(s + 1);  // latency hidden by MMAs below
            const uint32_t (*Af)[132] = As[buf];
            const uint32_t (*Bf)[132] = Bs[buf];
            MMA_ALL();
        }
    }

    EPI(0,0); EPI(0,1); EPI(0,2); EPI(0,3);
    EPI(1,0); EPI(1,1); EPI(1,2); EPI(1,3);
    EPI(2,0); EPI(2,1); EPI(2,2); EPI(2,3);
    EPI(3,0); EPI(3,1); EPI(3,2); EPI(3,3);
}

// ---------------- F3 partials over c-chunks of 64 ----------------
__global__ void k_f3p(const float* __restrict__ amp3, const float* __restrict__ pha3) {
    __shared__ float ws[NH * 64];
    int tid = threadIdx.x;
    int c0 = blockIdx.y * 64;
    int br = blockIdx.z;
    const float* W3 = br ? pha3 : amp3;
    const float* F2b = g_F2 + (size_t)br * DK * HW;
    for (int i = tid; i < NH * 64; i += 256) {
        int h = i >> 6, c = i & 63;
        ws[i] = W3[h * DK + c0 + c];
    }
    __syncthreads();
    int s = blockIdx.x * 256 + tid;
    if (s >= HW) return;
    float acc[NH] = {};
    for (int c = 0; c < 64; c++) {
        float v = fmaxf(F2b[(c0 + c) * HW + s], 0.f);
        #pragma unroll
        for (int h = 0; h < NH; h++) acc[h] += ws[h * 64 + c] * v;
    }
    #pragma unroll
    for (int h = 0; h < NH; h++)
        g_F3p[((size_t)br * 8 + blockIdx.y) * NH * HW + h * HW + s] = acc[h];
}

__global__ void k_f3red() {
    int idx = blockIdx.x * 256 + threadIdx.x;
    if (idx >= NH * HW) return;
    int br = blockIdx.y;
    const float* p = g_F3p + (size_t)br * 8 * NH * HW;
    float s = 0.f;
    #pragma unroll
    for (int i = 0; i < 8; i++) s += p[i * NH * HW + idx];
    g_F3[br * NH * HW + idx] = fmaxf(s, 0.f);
}

// ---------------- down-proj (warp per output j) ----------------
__global__ void k_down(const float* __restrict__ Wd1, const float* __restrict__ bd1,
                       const float* __restrict__ Wd2, const float* __restrict__ bd2) {
    int warp = threadIdx.x >> 5, lane = threadIdx.x & 31;
    int j = blockIdx.x * 8 + warp;
    int br = blockIdx.y;
    if (j >= HRW) return;
    const float* Wd = br ? Wd2 : Wd1;
    const float* bd = br ? bd2 : bd1;
    const float* F3b = g_F3 + br * NH * HW;
    const float* wr = Wd + (size_t)j * HW;
    float acc[NH] = {};
    for (int s = lane; s < HW; s += 32) {
        float wv = wr[s];
        #pragma unroll
        for (int h = 0; h < NH; h++) acc[h] += wv * F3b[h * HW + s];
    }
    #pragma unroll
    for (int h = 0; h < NH; h++) {
        #pragma unroll
        for (int o = 16; o > 0; o >>= 1) acc[h] += __shfl_down_sync(0xffffffffu, acc[h], o);
    }
    if (lane == 0) {
        float b = bd[j];
        #pragma unroll
        for (int h = 0; h < NH; h++) g_filt[br][h * HRW + j] = acc[h] + b;
    }
}

// ---------------- FFT chain ----------------
__global__ void k_fftrow() {
    int hy = blockIdx.x;
    int h = hy / HH, y = hy % HH;
    __shared__ float row[HH], twc[HH], tws[HH];
    int tid = threadIdx.x;  // 64
    for (int i = tid; i < HH; i += 64) {
        row[i] = g_A0[h * HW + y * WW + i];
        float sv, cv;
        sincosf(TWO_PI * (float)i / 65.f, &sv, &cv);
        twc[i] = cv; tws[i] = sv;
    }
    __syncthreads();
    if (tid < RW) {
        float re = 0.f, im = 0.f;
        for (int x = 0; x < HH; x++) {
            int t = (tid * x) % 65;
            re += row[x] * twc[t];
            im -= row[x] * tws[t];
        }
        g_Fr[h * HRW + y * RW + tid] = make_float2(re, im);
    }
}

__global__ void k_fftcol_mod() {
    __shared__ float twc[HH], tws[HH];
    for (int i = threadIdx.x; i < HH; i += 256) {
        float sv, cv;
        sincosf(TWO_PI * (float)i / 65.f, &sv, &cv);
        twc[i] = cv; tws[i] = sv;
    }
    __syncthreads();
    int idx = blockIdx.x * 256 + threadIdx.x;
    if (idx >= NH * HRW) return;
    int h = idx / HRW, r = idx % HRW;
    int ky = r / RW, kx = r % RW;
    const float2* fr = g_Fr + h * HRW + kx;
    float re = 0.f, im = 0.f;
    for (int y = 0; y < HH; y++) {
        int t = (ky * y) % 65;
        float c = twc[t], s = tws[t];
        float2 f = fr[y * RW];
        re += f.x * c + f.y * s;
        im += f.y * c - f.x * s;
    }
    float mag = sqrtf(re * re + im * im);
    float ang = atan2f(im, re);
    float a = g_filt[0][idx] * mag;
    float p = g_filt[1][idx] * ang;
    float sp, cp;
    sincosf(p, &sp, &cp);
    g_Af[idx] = make_float2(a * cp, a * sp);
}

__global__ void k_invcol() {
    __shared__ float twc[HH], tws[HH];
    for (int i = threadIdx.x; i < HH; i += 256) {
        float sv, cv;
        sincosf(TWO_PI * (float)i / 65.f, &sv, &cv);
        twc[i] = cv; tws[i] = sv;
    }
    __syncthreads();
    int idx = blockIdx.x * 256 + threadIdx.x;
    if (idx >= NH * HRW) return;
    int h = idx / HRW, r = idx % HRW;
    int y = r / RW, kx = r % RW;
    const float2* af = g_Af + h * HRW + kx;
    float re = 0.f, im = 0.f;
    for (int ky = 0; ky < HH; ky++) {
        int t = (ky * y) % 65;
        float c = twc[t], s = tws[t];
        float2 f = af[ky * RW];
        re += f.x * c - f.y * s;
        im += f.y * c + f.x * s;
    }
    g_Gr[idx] = make_float2(re * (1.f / 65.f), im * (1.f / 65.f));
}

__global__ void k_invrow() {
    __shared__ float twc[HH], tws[HH];
    for (int i = threadIdx.x; i < HH; i += 256) {
        float sv, cv;
        sincosf(TWO_PI * (float)i / 65.f, &sv, &cv);
        twc[i] = cv; tws[i] = sv;
    }
    __syncthreads();
    int idx = blockIdx.x * 256 + threadIdx.x;
    if (idx >= NH * HW) return;
    int h = idx / HW, s = idx % HW;
    int y = s / WW, x = s % WW;
    const float2* gp = g_Gr + h * HRW + y * RW;
    float acc = gp[0].x;
    for (int k = 1; k < RW; k++) {
        int t = (k * x) % 65;
        acc += 2.f * (gp[k].x * twc[t] - gp[k].y * tws[t]);
    }
    g_A[idx] = acc * (1.f / 65.f);
}

// ---------------- softmax per head ----------------
__global__ void k_softmax() {
    int h = blockIdx.x, tid = threadIdx.x;
    __shared__ float red[256];
    const float* a = g_A + h * HW;
    float* p = g_P + h * HW;
    float mx = -3.4e38f;
    for (int s = tid; s < HW; s += 256) mx = fmaxf(mx, a[s]);
    red[tid] = mx;
    __syncthreads();
    for (int st = 128; st > 0; st >>= 1) {
        if (tid < st) red[tid] = fmaxf(red[tid], red[tid + st]);
        __syncthreads();
    }
    mx = red[0];
    __syncthreads();
    float sum = 0.f;
    for (int s = tid; s < HW; s += 256) {
        float e = expf(a[s] - mx);
        p[s] = e;
        sum += e;
    }
    red[tid] = sum;
    __syncthreads();
    for (int st = 128; st > 0; st >>= 1) {
        if (tid < st) red[tid] += red[tid + st];
        __syncthreads();
    }
    float inv = 1.f / red[0];
    for (int s = tid; s < HW; s += 256) p[s] *= inv;
}

// ---------------- m[h,c] = sum_s P[h,s]*K[c,s] ----------------
__global__ void k_m(const float* __restrict__ K) {
    int c = blockIdx.x * 8 + (threadIdx.x >> 5);
    int lane = threadIdx.x & 31;
    const float* kr = K + c * HW;
    float acc[NH] = {};
    for (int s = lane; s < HW; s += 32) {
        float kv = kr[s];
        #pragma unroll
        for (int h = 0; h < NH; h++) acc[h] += kv * g_P[h * HW + s];
    }
    #pragma unroll
    for (int h = 0; h < NH; h++) {
        #pragma unroll
        for (int o = 16; o > 0; o >>= 1) acc[h] += __shfl_down_sync(0xffffffffu, acc[h], o);
    }
    if (lane == 0) {
        #pragma unroll
        for (int h = 0; h < NH; h++) g_m[h * DK + c] = acc[h];
    }
}

__global__ void k_vproj(const float* __restrict__ Wv, const float* __restrict__ bv) {
    int r = blockIdx.x * 8 + (threadIdx.x >> 5);
    int lane = threadIdx.x & 31;
    int h = r >> 9;
    const float* mr = g_m + (h << 9);
    const float* wr = Wv + r * DK;
    float acc = 0.f;
    for (int c = lane; c < DK; c += 32) acc += wr[c] * mr[c];
    #pragma unroll
    for (int o = 16; o > 0; o >>= 1) acc += __shfl_down_sync(0xffffffffu, acc, o);
    if (lane == 0) g_x[r] = acc + bv[r];
}

__global__ void k_out(const float* __restrict__ Wo, const float* __restrict__ bo,
                      float* __restrict__ out) {
    int r = blockIdx.x * 8 + (threadIdx.x >> 5);
    int lane = threadIdx.x & 31;
    const float* wr = Wo + r * DHID;
    float acc = 0.f;
    for (int j = lane; j < DHID; j += 32) acc += wr[j] * g_x[j];
    #pragma unroll
    for (int o = 16; o > 0; o >>= 1) acc += __shfl_down_sync(0xffffffffu, acc, o);
    if (lane == 0) out[r] = acc + bo[r];
}

extern "C" void kernel_launch(void* const* d_in, const int* in_sizes, int n_in,
                              void* d_out, int out_size) {
    const float* Q    = (const float*)d_in[0];
    const float* K    = (const float*)d_in[1];
    const float* Wq   = (const float*)d_in[2];
    const float* bq   = (const float*)d_in[3];
    const float* Wk   = (const float*)d_in[4];
    const float* bk   = (const float*)d_in[5];
    const float* Wv   = (const float*)d_in[6];
    const float* bv   = (const float*)d_in[7];
    const float* Wo   = (const float*)d_in[8];
    const float* bo   = (const float*)d_in[9];
    const float* amp1 = (const float*)d_in[10];
    const float* amp2 = (const float*)d_in[11];
    const float* amp3 = (const float*)d_in[12];
    const float* pha1 = (const float*)d_in[13];
    const float* pha2 = (const float*)d_in[14];
    const float* pha3 = (const float*)d_in[15];
    const float* Wd1  = (const float*)d_in[16];
    const float* bd1  = (const float*)d_in[17];
    const float* Wd2  = (const float*)d_in[18];
    const float* bd2  = (const float*)d_in[19];
    float* out = (float*)d_out;

    // conv path first: positions k_mma<1> at launch #4 (where ncu samples)
    k_tr1<<<dim3(16, 16, 2), dim3(32, 8)>>>(amp1, pha1);                 // 1
    k_tr2<<<dim3(18, 16, 16), dim3(32, 8)>>>(amp2, pha2);                // 2
    k_mma<0><<<dim3(34, 8, 1), 256>>>(K);                                // 3
    k_mma<1><<<dim3(34, 4, 2), 256>>>(K);                                // 4

    // attention-score path
    k_qproj<<<512, 256>>>(Q, Wq, bq);
    k_qb<<<1, 256>>>(bk);
    k_u<<<dim3(8, 8), 512>>>(Wk);
    k_A0p<<<dim3(17, 8), 256>>>(K);
    k_A0red<<<133, 256>>>();

    k_f3p<<<dim3(17, 8, 2), 256>>>(amp3, pha3);
    k_f3red<<<dim3(133, 2), 256>>>();
    k_down<<<dim3(269, 2), 256>>>(Wd1, bd1, Wd2, bd2);

    // spectral filtering
    k_fftrow<<<NH * HH, 64>>>();
    k_fftcol_mod<<<68, 256>>>();
    k_invcol<<<68, 256>>>();
    k_invrow<<<133, 256>>>();
    k_softmax<<<NH, 256>>>();

    // output path
    k_m<<<64, 256>>>(K);
    k_vproj<<<512, 256>>>(Wv, bv);
    k_out<<<64, 256>>>(Wo, bo, out);
}

// round 10
// speedup vs baseline: 1.1157x; 1.0718x over previous
#include <cuda_runtime.h>
#include <math.h>
#include <stdint.h>

#define HH 65
#define WW 65
#define HW 4225
#define NH 8
#define DK 512
#define RW 33
#define HRW 2145
#define DHID 4096

// ---------------- scratch (device globals) ----------------
__device__ float g_q[DHID];
__device__ float g_up[8 * 4096];
__device__ float g_qb[NH];
__device__ float g_A0p[8 * NH * HW];
__device__ float g_A0[NH * HW];
__device__ float g_Wt1[DK * 1024];        // tf32 bits, [k][br*512+o]
__device__ float g_Wt2[2 * 9 * DK * DK];  // tf32 bits, [br*9+t][i][o]
__device__ float g_F1[2 * DK * HW];       // fp32 (for residual)
__device__ uint32_t g_F1t[2 * DK * HW];   // tf32 bits of relu(F1)
__device__ float g_F2[2 * DK * HW];
__device__ float g_F3p[2 * 8 * NH * HW];
__device__ float g_F3[2 * NH * HW];
__device__ float g_filt[2][NH * HRW];
__device__ float2 g_Fr[NH * HRW];
__device__ float2 g_Af[NH * HRW];
__device__ float2 g_Gr[NH * HRW];
__device__ float g_A[NH * HW];
__device__ float g_P[NH * HW];
__device__ float g_m[NH * DK];
__device__ float g_x[DHID];

#define TWO_PI 6.28318530717958647692f

__device__ __forceinline__ uint32_t f2tf32(float f) {
    uint32_t u;
    asm("cvt.rna.tf32.f32 %0, %1;" : "=r"(u) : "f"(f));
    return u;
}

__device__ __forceinline__ void mma_tf32(
    float& c0, float& c1, float& c2, float& c3,
    uint32_t a0, uint32_t a1, uint32_t a2, uint32_t a3,
    uint32_t b0, uint32_t b1) {
    asm volatile(
        "mma.sync.aligned.m16n8k8.row.col.f32.tf32.tf32.f32 "
        "{%0,%1,%2,%3},{%4,%5,%6,%7},{%8,%9},{%0,%1,%2,%3};"
        : "+f"(c0), "+f"(c1), "+f"(c2), "+f"(c3)
        : "r"(a0), "r"(a1), "r"(a2), "r"(a3), "r"(b0), "r"(b1));
}

// ---------------- q = Wq @ Q + bq ----------------
__global__ void k_qproj(const float* __restrict__ Q, const float* __restrict__ Wq,
                        const float* __restrict__ bq) {
    int r = blockIdx.x * 8 + (threadIdx.x >> 5);
    int lane = threadIdx.x & 31;
    const float* wr = Wq + r * DK;
    float acc = 0.f;
    for (int c = lane; c < DK; c += 32) acc += wr[c] * Q[c];
    #pragma unroll
    for (int o = 16; o > 0; o >>= 1) acc += __shfl_down_sync(0xffffffffu, acc, o);
    if (lane == 0) g_q[r] = acc + bq[r];
}

// ---------------- qb[h] = q_h . bk_h ----------------
__global__ void k_qb(const float* __restrict__ bk) {
    int h = threadIdx.x >> 5, lane = threadIdx.x & 31;
    float acc = 0.f;
    for (int d = lane; d < DK; d += 32) acc += g_q[h * DK + d] * bk[h * DK + d];
    #pragma unroll
    for (int o = 16; o > 0; o >>= 1) acc += __shfl_down_sync(0xffffffffu, acc, o);
    if (lane == 0) g_qb[h] = acc;
}

// ---------------- u partials ----------------
__global__ void k_u(const float* __restrict__ Wk) {
    int h = blockIdx.x, p = blockIdx.y;
    int tid = threadIdx.x;  // 512
    __shared__ float qs[64];
    if (tid < 64) qs[tid] = g_q[h * DK + p * 64 + tid];
    __syncthreads();
    float acc = 0.f;
    const float* wb = Wk + h * DK * DK + (p * 64) * DK + tid;
    #pragma unroll 8
    for (int d = 0; d < 64; d++) acc += wb[d * DK] * qs[d];
    g_up[p * 4096 + h * DK + tid] = acc;
}

// ---------------- A0 partials over c-chunks of 64 ----------------
__global__ void k_A0p(const float* __restrict__ K) {
    __shared__ float us[NH * 64];
    int tid = threadIdx.x;
    int c0 = blockIdx.y * 64;
    for (int i = tid; i < NH * 64; i += 256) {
        int h = i >> 6, c = i & 63;
        float s = 0.f;
        #pragma unroll
        for (int p = 0; p < 8; p++) s += g_up[p * 4096 + h * DK + c0 + c];
        us[i] = s;
    }
    __syncthreads();
    int s = blockIdx.x * 256 + tid;
    if (s >= HW) return;
    float acc[NH] = {};
    for (int c = 0; c < 64; c++) {
        float kv = K[(c0 + c) * HW + s];
        #pragma unroll
        for (int h = 0; h < NH; h++) acc[h] += us[h * 64 + c] * kv;
    }
    #pragma unroll
    for (int h = 0; h < NH; h++) g_A0p[blockIdx.y * NH * HW + h * HW + s] = acc[h];
}

__global__ void k_A0red() {
    int idx = blockIdx.x * 256 + threadIdx.x;
    if (idx >= NH * HW) return;
    int h = idx / HW;
    float s = 0.f;
    #pragma unroll
    for (int p = 0; p < 8; p++) s += g_A0p[p * NH * HW + idx];
    g_A0[idx] = (s + g_qb[h]) * 0.04419417382415922f;
}

// ---------------- tiled weight transposes (store tf32 bits) ----------------
__global__ void k_tr1(const float* __restrict__ amp1, const float* __restrict__ pha1) {
    __shared__ float tile[32][33];
    int br = blockIdx.z;
    const float* src = br ? pha1 : amp1;
    int o0 = blockIdx.x * 32, i0 = blockIdx.y * 32;
    int tx = threadIdx.x, ty = threadIdx.y;
    #pragma unroll
    for (int r = 0; r < 32; r += 8)
        tile[ty + r][tx] = src[(o0 + ty + r) * DK + i0 + tx];
    __syncthreads();
    #pragma unroll
    for (int r = 0; r < 32; r += 8)
        g_Wt1[(i0 + ty + r) * 1024 + br * DK + o0 + tx] = __uint_as_float(f2tf32(tile[tx][ty + r]));
}

__global__ void k_tr2(const float* __restrict__ amp2, const float* __restrict__ pha2) {
    __shared__ float tile[32][33];
    int bt = blockIdx.x;           // br*9 + t
    int br = bt / 9, t = bt % 9;
    const float* src = br ? pha2 : amp2;
    int o0 = blockIdx.y * 32, i0 = blockIdx.z * 32;
    int tx = threadIdx.x, ty = threadIdx.y;
    #pragma unroll
    for (int r = 0; r < 32; r += 8)
        tile[ty + r][tx] = src[((o0 + ty + r) * DK + i0 + tx) * 9 + t];
    __syncthreads();
    #pragma unroll
    for (int r = 0; r < 32; r += 8)
        g_Wt2[((size_t)bt * DK + i0 + ty + r) * DK + o0 + tx] = __uint_as_float(f2tf32(tile[tx][ty + r]));
}

// ---------------- tf32 tensor-core GEMM / implicit conv ----------------
// Permuted smem layouts enabling LDS.128 fragment loads:
//   A: logical m = w*64 + j*8 + g  ->  lin = w*64 + g*8 + j, phys = lin + 4*(lin>>5)
//      (row stride 140; 4-word pad per 32-group makes scalar writes conflict-free)
//   B: logical n = c32*32 + nf*8 + g -> phys = c32*32 + g*4 + nf
//      (row stride 136 ≡ 8 mod 32: vector reads conflict-free, writes conflict-free)

#define RA 140
#define RB 136

#define DECL_ACC(M,N) float c##M##N##x = 0.f, c##M##N##y = 0.f, c##M##N##z = 0.f, c##M##N##w = 0.f

#define MMA_ALL() do { \
    _Pragma("unroll") \
    for (int kf = 0; kf < 2; kf++) { \
        int r0 = kf * 8 + tg, r1 = r0 + 4; \
        uint4 aL0 = *(const uint4*)&Af[r0][apix]; \
        uint4 aH0 = *(const uint4*)&Af[r0][apix + 4]; \
        uint4 aL1 = *(const uint4*)&Af[r1][apix]; \
        uint4 aH1 = *(const uint4*)&Af[r1][apix + 4]; \
        uint4 b0  = *(const uint4*)&Bf[r0][bpix]; \
        uint4 b1  = *(const uint4*)&Bf[r1][bpix]; \
        mma_tf32(c00x,c00y,c00z,c00w, aL0.x,aL0.y,aL1.x,aL1.y, b0.x,b1.x); \
        mma_tf32(c01x,c01y,c01z,c01w, aL0.x,aL0.y,aL1.x,aL1.y, b0.y,b1.y); \
        mma_tf32(c02x,c02y,c02z,c02w, aL0.x,aL0.y,aL1.x,aL1.y, b0.z,b1.z); \
        mma_tf32(c03x,c03y,c03z,c03w, aL0.x,aL0.y,aL1.x,aL1.y, b0.w,b1.w); \
        mma_tf32(c10x,c10y,c10z,c10w, aL0.z,aL0.w,aL1.z,aL1.w, b0.x,b1.x); \
        mma_tf32(c11x,c11y,c11z,c11w, aL0.z,aL0.w,aL1.z,aL1.w, b0.y,b1.y); \
        mma_tf32(c12x,c12y,c12z,c12w, aL0.z,aL0.w,aL1.z,aL1.w, b0.z,b1.z); \
        mma_tf32(c13x,c13y,c13z,c13w, aL0.z,aL0.w,aL1.z,aL1.w, b0.w,b1.w); \
        mma_tf32(c20x,c20y,c20z,c20w, aH0.x,aH0.y,aH1.x,aH1.y, b0.x,b1.x); \
        mma_tf32(c21x,c21y,c21z,c21w, aH0.x,aH0.y,aH1.x,aH1.y, b0.y,b1.y); \
        mma_tf32(c22x,c22y,c22z,c22w, aH0.x,aH0.y,aH1.x,aH1.y, b0.z,b1.z); \
        mma_tf32(c23x,c23y,c23z,c23w, aH0.x,aH0.y,aH1.x,aH1.y, b0.w,b1.w); \
        mma_tf32(c30x,c30y,c30z,c30w, aH0.z,aH0.w,aH1.z,aH1.w, b0.x,b1.x); \
        mma_tf32(c31x,c31y,c31z,c31w, aH0.z,aH0.w,aH1.z,aH1.w, b0.y,b1.y); \
        mma_tf32(c32x,c32y,c32z,c32w, aH0.z,aH0.w,aH1.z,aH1.w, b0.z,b1.z); \
        mma_tf32(c33x,c33y,c33z,c33w, aH0.z,aH0.w,aH1.z,aH1.w, b0.w,b1.w); \
    } \
} while (0)

// Prefetch one 16-row slice into 16 named scalars.
#define LDSLICE(s) do { \
    int t_ = (s) >> 5; \
    int kc_ = ((s) & 31) << 4; \
    int dy_ = t_ / 3 - 1, dx_ = t_ % 3 - 1; \
    int yy_ = ny + dy_, xx_ = nx + dx_; \
    bool ok_ = nvalid && (unsigned)yy_ < HH && (unsigned)xx_ < WW; \
    int src_ = ok_ ? (yy_ * WW + xx_) : 0; \
    const uint32_t* wrow_ = Wt2u + ((size_t)(z * 9 + t_) * DK + kc_) * DK + m0 + col; \
    const uint32_t* xrow_ = F1tz + (size_t)kc_ * HW + src_; \
    ra0 = wrow_[(size_t)(0 + krow0) * DK];  rb0 = ok_ ? xrow_[(size_t)(0 + krow0) * HW] : 0u; \
    ra1 = wrow_[(size_t)(2 + krow0) * DK];  rb1 = ok_ ? xrow_[(size_t)(2 + krow0) * HW] : 0u; \
    ra2 = wrow_[(size_t)(4 + krow0) * DK];  rb2 = ok_ ? xrow_[(size_t)(4 + krow0) * HW] : 0u; \
    ra3 = wrow_[(size_t)(6 + krow0) * DK];  rb3 = ok_ ? xrow_[(size_t)(6 + krow0) * HW] : 0u; \
    ra4 = wrow_[(size_t)(8 + krow0) * DK];  rb4 = ok_ ? xrow_[(size_t)(8 + krow0) * HW] : 0u; \
    ra5 = wrow_[(size_t)(10 + krow0) * DK]; rb5 = ok_ ? xrow_[(size_t)(10 + krow0) * HW] : 0u; \
    ra6 = wrow_[(size_t)(12 + krow0) * DK]; rb6 = ok_ ? xrow_[(size_t)(12 + krow0) * HW] : 0u; \
    ra7 = wrow_[(size_t)(14 + krow0) * DK]; rb7 = ok_ ? xrow_[(size_t)(14 + krow0) * HW] : 0u; \
} while (0)

#define STSLICE(buf) do { \
    As[buf][0 + krow0][physA] = ra0;  Bs[buf][0 + krow0][physB] = rb0; \
    As[buf][2 + krow0][physA] = ra1;  Bs[buf][2 + krow0][physB] = rb1; \
    As[buf][4 + krow0][physA] = ra2;  Bs[buf][4 + krow0][physB] = rb2; \
    As[buf][6 + krow0][physA] = ra3;  Bs[buf][6 + krow0][physB] = rb3; \
    As[buf][8 + krow0][physA] = ra4;  Bs[buf][8 + krow0][physB] = rb4; \
    As[buf][10 + krow0][physA] = ra5; Bs[buf][10 + krow0][physB] = rb5; \
    As[buf][12 + krow0][physA] = ra6; Bs[buf][12 + krow0][physB] = rb6; \
    As[buf][14 + krow0][physA] = ra7; Bs[buf][14 + krow0][physB] = rb7; \
} while (0)

#define STORE1(val, mrow, nc) do { \
    if (MODE == 0) { \
        float v_ = (val); \
        Yb[(size_t)(mrow) * HW + (nc)] = v_; \
        g_F1t[(size_t)(mrow) * HW + (nc)] = f2tf32(fmaxf(v_, 0.f)); \
    } else { \
        Yb[(size_t)(mrow) * HW + (nc)] = (val) + Rb[(size_t)(mrow) * HW + (nc)]; \
    } \
} while (0)

#define EPI(M,N) do { \
    int mrow = m0 + wm + M*16 + g; \
    int nc = n0 + wn + N*8 + tg*2; \
    if (nc < HW) { \
        STORE1(c##M##N##x, mrow, nc); \
        STORE1(c##M##N##z, mrow + 8, nc); \
        if (nc + 1 < HW) { \
            STORE1(c##M##N##y, mrow, nc + 1); \
            STORE1(c##M##N##w, mrow + 8, nc + 1); \
        } \
    } \
} while (0)

template <int MODE>
__global__ void __launch_bounds__(256) k_mma(const float* __restrict__ Kin) {
    __shared__ __align__(16) uint32_t As[2][16][RA];
    __shared__ __align__(16) uint32_t Bs[2][16][RB];
    int tid = threadIdx.x;
    int n0 = blockIdx.x * 128, m0 = blockIdx.y * 128;
    int z = blockIdx.z;

    int col = tid & 127;
    int krow0 = tid >> 7;         // 0 or 1
    int n = n0 + col;
    bool nvalid = n < HW;
    int ny = n / WW, nx = n - ny * WW;

    // writer phys indices (per-thread constants)
    int linA = (col >> 6) * 64 + (col & 7) * 8 + ((col >> 3) & 7);
    int physA = linA + 4 * (linA >> 5);
    int physB = (col >> 5) * 32 + (col & 7) * 4 + ((col >> 3) & 3);

    int warp = tid >> 5, lane = tid & 31;
    int wm = (warp & 1) * 64, wn = (warp >> 1) * 32;
    int g = lane >> 2, tg = lane & 3;

    // reader phys bases
    int linr = wm + g * 8;
    int apix = linr + 4 * (linr >> 5);
    int bpix = wn + g * 4;

    float* Yb;
    const float* Rb;
    if (MODE == 0) { Yb = g_F1; Rb = g_F1; }
    else { Yb = g_F2 + (size_t)z * DK * HW; Rb = g_F1 + (size_t)z * DK * HW; }

    DECL_ACC(0,0); DECL_ACC(0,1); DECL_ACC(0,2); DECL_ACC(0,3);
    DECL_ACC(1,0); DECL_ACC(1,1); DECL_ACC(1,2); DECL_ACC(1,3);
    DECL_ACC(2,0); DECL_ACC(2,1); DECL_ACC(2,2); DECL_ACC(2,3);
    DECL_ACC(3,0); DECL_ACC(3,1); DECL_ACC(3,2); DECL_ACC(3,3);

    if (MODE == 0) {
        const uint32_t* Wt1u = (const uint32_t*)g_Wt1;
        for (int kc = 0; kc < DK; kc += 16) {
            #pragma unroll
            for (int i = 0; i < 8; i++) {
                int kr = i * 2 + krow0;
                As[0][kr][physA] = Wt1u[(size_t)(kc + kr) * 1024 + m0 + col];
                Bs[0][kr][physB] = f2tf32(nvalid ? Kin[(kc + kr) * HW + n] : 0.f);
            }
            __syncthreads();
            const uint32_t (*Af)[RA] = As[0];
            const uint32_t (*Bf)[RB] = Bs[0];
            MMA_ALL();
            __syncthreads();
        }
    } else {
        const int S = 9 * 32;
        const uint32_t* Wt2u = (const uint32_t*)g_Wt2;
        const uint32_t* F1tz = g_F1t + (size_t)z * DK * HW;
        uint32_t ra0, ra1, ra2, ra3, ra4, ra5, ra6, ra7;
        uint32_t rb0, rb1, rb2, rb3, rb4, rb5, rb6, rb7;
        LDSLICE(0);
        for (int s = 0; s < S; s++) {
            int buf = s & 1;
            STSLICE(buf);
            __syncthreads();
            if (s + 1 < S) LDSLICE(s + 1);  // latency hidden by MMAs below
            const uint32_t (*Af)[RA] = As[buf];
            const uint32_t (*Bf)[RB] = Bs[buf];
            MMA_ALL();
        }
    }

    EPI(0,0); EPI(0,1); EPI(0,2); EPI(0,3);
    EPI(1,0); EPI(1,1); EPI(1,2); EPI(1,3);
    EPI(2,0); EPI(2,1); EPI(2,2); EPI(2,3);
    EPI(3,0); EPI(3,1); EPI(3,2); EPI(3,3);
}

// ---------------- F3 partials over c-chunks of 64 ----------------
__global__ void k_f3p(const float* __restrict__ amp3, const float* __restrict__ pha3) {
    __shared__ float ws[NH * 64];
    int tid = threadIdx.x;
    int c0 = blockIdx.y * 64;
    int br = blockIdx.z;
    const float* W3 = br ? pha3 : amp3;
    const float* F2b = g_F2 + (size_t)br * DK * HW;
    for (int i = tid; i < NH * 64; i += 256) {
        int h = i >> 6, c = i & 63;
        ws[i] = W3[h * DK + c0 + c];
    }
    __syncthreads();
    int s = blockIdx.x * 256 + tid;
    if (s >= HW) return;
    float acc[NH] = {};
    for (int c = 0; c < 64; c++) {
        float v = fmaxf(F2b[(c0 + c) * HW + s], 0.f);
        #pragma unroll
        for (int h = 0; h < NH; h++) acc[h] += ws[h * 64 + c] * v;
    }
    #pragma unroll
    for (int h = 0; h < NH; h++)
        g_F3p[((size_t)br * 8 + blockIdx.y) * NH * HW + h * HW + s] = acc[h];
}

__global__ void k_f3red() {
    int idx = blockIdx.x * 256 + threadIdx.x;
    if (idx >= NH * HW) return;
    int br = blockIdx.y;
    const float* p = g_F3p + (size_t)br * 8 * NH * HW;
    float s = 0.f;
    #pragma unroll
    for (int i = 0; i < 8; i++) s += p[i * NH * HW + idx];
    g_F3[br * NH * HW + idx] = fmaxf(s, 0.f);
}

// ---------------- down-proj (warp per output j) ----------------
__global__ void k_down(const float* __restrict__ Wd1, const float* __restrict__ bd1,
                       const float* __restrict__ Wd2, const float* __restrict__ bd2) {
    int warp = threadIdx.x >> 5, lane = threadIdx.x & 31;
    int j = blockIdx.x * 8 + warp;
    int br = blockIdx.y;
    if (j >= HRW) return;
    const float* Wd = br ? Wd2 : Wd1;
    const float* bd = br ? bd2 : bd1;
    const float* F3b = g_F3 + br * NH * HW;
    const float* wr = Wd + (size_t)j * HW;
    float acc[NH] = {};
    for (int s = lane; s < HW; s += 32) {
        float wv = wr[s];
        #pragma unroll
        for (int h = 0; h < NH; h++) acc[h] += wv * F3b[h * HW + s];
    }
    #pragma unroll
    for (int h = 0; h < NH; h++) {
        #pragma unroll
        for (int o = 16; o > 0; o >>= 1) acc[h] += __shfl_down_sync(0xffffffffu, acc[h], o);
    }
    if (lane == 0) {
        float b = bd[j];
        #pragma unroll
        for (int h = 0; h < NH; h++) g_filt[br][h * HRW + j] = acc[h] + b;
    }
}

// ---------------- FFT chain ----------------
__global__ void k_fftrow() {
    int hy = blockIdx.x;
    int h = hy / HH, y = hy % HH;
    __shared__ float row[HH], twc[HH], tws[HH];
    int tid = threadIdx.x;  // 64
    for (int i = tid; i < HH; i += 64) {
        row[i] = g_A0[h * HW + y * WW + i];
        float sv, cv;
        sincosf(TWO_PI * (float)i / 65.f, &sv, &cv);
        twc[i] = cv; tws[i] = sv;
    }
    __syncthreads();
    if (tid < RW) {
        float re = 0.f, im = 0.f;
        for (int x = 0; x < HH; x++) {
            int t = (tid * x) % 65;
            re += row[x] * twc[t];
            im -= row[x] * tws[t];
        }
        g_Fr[h * HRW + y * RW + tid] = make_float2(re, im);
    }
}

__global__ void k_fftcol_mod() {
    __shared__ float twc[HH], tws[HH];
    for (int i = threadIdx.x; i < HH; i += 256) {
        float sv, cv;
        sincosf(TWO_PI * (float)i / 65.f, &sv, &cv);
        twc[i] = cv; tws[i] = sv;
    }
    __syncthreads();
    int idx = blockIdx.x * 256 + threadIdx.x;
    if (idx >= NH * HRW) return;
    int h = idx / HRW, r = idx % HRW;
    int ky = r / RW, kx = r % RW;
    const float2* fr = g_Fr + h * HRW + kx;
    float re = 0.f, im = 0.f;
    for (int y = 0; y < HH; y++) {
        int t = (ky * y) % 65;
        float c = twc[t], s = tws[t];
        float2 f = fr[y * RW];
        re += f.x * c + f.y * s;
        im += f.y * c - f.x * s;
    }
    float mag = sqrtf(re * re + im * im);
    float ang = atan2f(im, re);
    float a = g_filt[0][idx] * mag;
    float p = g_filt[1][idx] * ang;
    float sp, cp;
    sincosf(p, &sp, &cp);
    g_Af[idx] = make_float2(a * cp, a * sp);
}

__global__ void k_invcol() {
    __shared__ float twc[HH], tws[HH];
    for (int i = threadIdx.x; i < HH; i += 256) {
        float sv, cv;
        sincosf(TWO_PI * (float)i / 65.f, &sv, &cv);
        twc[i] = cv; tws[i] = sv;
    }
    __syncthreads();
    int idx = blockIdx.x * 256 + threadIdx.x;
    if (idx >= NH * HRW) return;
    int h = idx / HRW, r = idx % HRW;
    int y = r / RW, kx = r % RW;
    const float2* af = g_Af + h * HRW + kx;
    float re = 0.f, im = 0.f;
    for (int ky = 0; ky < HH; ky++) {
        int t = (ky * y) % 65;
        float c = twc[t], s = tws[t];
        float2 f = af[ky * RW];
        re += f.x * c - f.y * s;
        im += f.y * c + f.x * s;
    }
    g_Gr[idx] = make_float2(re * (1.f / 65.f), im * (1.f / 65.f));
}

__global__ void k_invrow() {
    __shared__ float twc[HH], tws[HH];
    for (int i = threadIdx.x; i < HH; i += 256) {
        float sv, cv;
        sincosf(TWO_PI * (float)i / 65.f, &sv, &cv);
        twc[i] = cv; tws[i] = sv;
    }
    __syncthreads();
    int idx = blockIdx.x * 256 + threadIdx.x;
    if (idx >= NH * HW) return;
    int h = idx / HW, s = idx % HW;
    int y = s / WW, x = s % WW;
    const float2* gp = g_Gr + h * HRW + y * RW;
    float acc = gp[0].x;
    for (int k = 1; k < RW; k++) {
        int t = (k * x) % 65;
        acc += 2.f * (gp[k].x * twc[t] - gp[k].y * tws[t]);
    }
    g_A[idx] = acc * (1.f / 65.f);
}

// ---------------- softmax per head ----------------
__global__ void k_softmax() {
    int h = blockIdx.x, tid = threadIdx.x;
    __shared__ float red[256];
    const float* a = g_A + h * HW;
    float* p = g_P + h * HW;
    float mx = -3.4e38f;
    for (int s = tid; s < HW; s += 256) mx = fmaxf(mx, a[s]);
    red[tid] = mx;
    __syncthreads();
    for (int st = 128; st > 0; st >>= 1) {
        if (tid < st) red[tid] = fmaxf(red[tid], red[tid + st]);
        __syncthreads();
    }
    mx = red[0];
    __syncthreads();
    float sum = 0.f;
    for (int s = tid; s < HW; s += 256) {
        float e = expf(a[s] - mx);
        p[s] = e;
        sum += e;
    }
    red[tid] = sum;
    __syncthreads();
    for (int st = 128; st > 0; st >>= 1) {
        if (tid < st) red[tid] += red[tid + st];
        __syncthreads();
    }
    float inv = 1.f / red[0];
    for (int s = tid; s < HW; s += 256) p[s] *= inv;
}

// ---------------- m[h,c] = sum_s P[h,s]*K[c,s] ----------------
__global__ void k_m(const float* __restrict__ K) {
    int c = blockIdx.x * 8 + (threadIdx.x >> 5);
    int lane = threadIdx.x & 31;
    const float* kr = K + c * HW;
    float acc[NH] = {};
    for (int s = lane; s < HW; s += 32) {
        float kv = kr[s];
        #pragma unroll
        for (int h = 0; h < NH; h++) acc[h] += kv * g_P[h * HW + s];
    }
    #pragma unroll
    for (int h = 0; h < NH; h++) {
        #pragma unroll
        for (int o = 16; o > 0; o >>= 1) acc[h] += __shfl_down_sync(0xffffffffu, acc[h], o);
    }
    if (lane == 0) {
        #pragma unroll
        for (int h = 0; h < NH; h++) g_m[h * DK + c] = acc[h];
    }
}

__global__ void k_vproj(const float* __restrict__ Wv, const float* __restrict__ bv) {
    int r = blockIdx.x * 8 + (threadIdx.x >> 5);
    int lane = threadIdx.x & 31;
    int h = r >> 9;
    const float* mr = g_m + (h << 9);
    const float* wr = Wv + r * DK;
    float acc = 0.f;
    for (int c = lane; c < DK; c += 32) acc += wr[c] * mr[c];
    #pragma unroll
    for (int o = 16; o > 0; o >>= 1) acc += __shfl_down_sync(0xffffffffu, acc, o);
    if (lane == 0) g_x[r] = acc + bv[r];
}

__global__ void k_out(const float* __restrict__ Wo, const float* __restrict__ bo,
                      float* __restrict__ out) {
    int r = blockIdx.x * 8 + (threadIdx.x >> 5);
    int lane = threadIdx.x & 31;
    const float* wr = Wo + r * DHID;
    float acc = 0.f;
    for (int j = lane; j < DHID; j += 32) acc += wr[j] * g_x[j];
    #pragma unroll
    for (int o = 16; o > 0; o >>= 1) acc += __shfl_down_sync(0xffffffffu, acc, o);
    if (lane == 0) out[r] = acc + bo[r];
}

extern "C" void kernel_launch(void* const* d_in, const int* in_sizes, int n_in,
                              void* d_out, int out_size) {
    const float* Q    = (const float*)d_in[0];
    const float* K    = (const float*)d_in[1];
    const float* Wq   = (const float*)d_in[2];
    const float* bq   = (const float*)d_in[3];
    const float* Wk   = (const float*)d_in[4];
    const float* bk   = (const float*)d_in[5];
    const float* Wv   = (const float*)d_in[6];
    const float* bv   = (const float*)d_in[7];
    const float* Wo   = (const float*)d_in[8];
    const float* bo   = (const float*)d_in[9];
    const float* amp1 = (const float*)d_in[10];
    const float* amp2 = (const float*)d_in[11];
    const float* amp3 = (const float*)d_in[12];
    const float* pha1 = (const float*)d_in[13];
    const float* pha2 = (const float*)d_in[14];
    const float* pha3 = (const float*)d_in[15];
    const float* Wd1  = (const float*)d_in[16];
    const float* bd1  = (const float*)d_in[17];
    const float* Wd2  = (const float*)d_in[18];
    const float* bd2  = (const float*)d_in[19];
    float* out = (float*)d_out;

    // conv path first: positions k_mma<1> at launch #4 (where ncu samples)
    k_tr1<<<dim3(16, 16, 2), dim3(32, 8)>>>(amp1, pha1);                 // 1
    k_tr2<<<dim3(18, 16, 16), dim3(32, 8)>>>(amp2, pha2);                // 2
    k_mma<0><<<dim3(34, 8, 1), 256>>>(K);                                // 3
    k_mma<1><<<dim3(34, 4, 2), 256>>>(K);                                // 4

    // attention-score path
    k_qproj<<<512, 256>>>(Q, Wq, bq);
    k_qb<<<1, 256>>>(bk);
    k_u<<<dim3(8, 8), 512>>>(Wk);
    k_A0p<<<dim3(17, 8), 256>>>(K);
    k_A0red<<<133, 256>>>();

    k_f3p<<<dim3(17, 8, 2), 256>>>(amp3, pha3);
    k_f3red<<<dim3(133, 2), 256>>>();
    k_down<<<dim3(269, 2), 256>>>(Wd1, bd1, Wd2, bd2);

    // spectral filtering
    k_fftrow<<<NH * HH, 64>>>();
    k_fftcol_mod<<<68, 256>>>();
    k_invcol<<<68, 256>>>();
    k_invrow<<<133, 256>>>();
    k_softmax<<<NH, 256>>>();

    // output path
    k_m<<<64, 256>>>(K);
    k_vproj<<<512, 256>>>(Wv, bv);
    k_out<<<64, 256>>>(Wo, bo, out);
}